// round 14
// baseline (speedup 1.0000x reference)
#include <cuda_runtime.h>
#include <cuda_bf16.h>
#include <cuda_fp16.h>
#include <cstdint>
#include <cstddef>

#define S_LEN   2048
#define DKD     64
#define BHN     32
#define MQT     64           // q rows per CTA
#define NKC     64           // k cols per chunk
#define NCH     (S_LEN / NKC)   // 32
#define NQT     (S_LEN / MQT)   // 32
#define THREADS 256

// 0.125 * log2(e): fold softmax scale + exp->exp2 conversion into Q
#define QSCALE 0.1803368801111831f

#define TILE_B  8192         // one 64x64 bf16 K/V tile, SW128 swizzled, 128B rows
#define CHUNK_B 32768        // Khi,Klo,Vhi,Vlo per chunk
#define QTILE_B 8192         // 64x64 bf16 Q tile
#define PS_STR  72           // p-staging row stride in halves (144B, conflict-free)

// ---- smem byte offsets ----
#define O_BUF0 0
#define O_BUF1 32768
#define O_QS   65536         // Q staging (16KB) at startup; p-staging tile (9.2KB) in loop
#define O_RED  81920         // 64 floats
#define O_INV  82176         // 64 floats
#define SMEMB  82432

#define SWZ(o) ((o) ^ (((o) >> 3) & 0x70))

// bf16 hi/lo K,V tiles, pre-swizzled ldmatrix-ready images (32 MB scratch)
__device__ __align__(16) unsigned char g_kv16[(size_t)BHN * NCH * CHUNK_B];
// unnormalized softmax numerators staged as fp16 (256 MB scratch), [bh][q][k] row-major
__device__ __align__(16) __half g_pstage[(size_t)BHN * S_LEN * S_LEN];
__device__ int g_mask_wide;

// ---------------- helpers ----------------
__device__ __forceinline__ uint32_t smem_u32(const void* p) {
    uint32_t a;
    asm("{ .reg .u64 t; cvta.to.shared.u64 t, %1; cvt.u32.u64 %0, t; }" : "=r"(a) : "l"(p));
    return a;
}
__device__ __forceinline__ float ex2f(float x) {
    float y; asm("ex2.approx.f32 %0, %1;" : "=f"(y) : "f"(x)); return y;
}
__device__ __forceinline__ uint32_t pkbf(float lo, float hi) {  // lo -> bits[15:0]
    uint32_t r; asm("cvt.rn.bf16x2.f32 %0, %1, %2;" : "=r"(r) : "f"(hi), "f"(lo)); return r;
}
__device__ __forceinline__ void ldsm4(uint32_t a, uint32_t& r0, uint32_t& r1, uint32_t& r2, uint32_t& r3) {
    asm volatile("ldmatrix.sync.aligned.m8n8.x4.shared.b16 {%0,%1,%2,%3}, [%4];"
                 : "=r"(r0), "=r"(r1), "=r"(r2), "=r"(r3) : "r"(a));
}
__device__ __forceinline__ void ldsm4t(uint32_t a, uint32_t& r0, uint32_t& r1, uint32_t& r2, uint32_t& r3) {
    asm volatile("ldmatrix.sync.aligned.m8n8.x4.trans.shared.b16 {%0,%1,%2,%3}, [%4];"
                 : "=r"(r0), "=r"(r1), "=r"(r2), "=r"(r3) : "r"(a));
}
__device__ __forceinline__ void mma16816(float* c, const uint32_t* A, uint32_t b0, uint32_t b1) {
    asm volatile("mma.sync.aligned.m16n8k16.row.col.f32.bf16.bf16.f32 "
                 "{%0,%1,%2,%3}, {%4,%5,%6,%7}, {%8,%9}, {%0,%1,%2,%3};"
                 : "+f"(c[0]), "+f"(c[1]), "+f"(c[2]), "+f"(c[3])
                 : "r"(A[0]), "r"(A[1]), "r"(A[2]), "r"(A[3]), "r"(b0), "r"(b1));
}
#define CP16(dst, src) asm volatile("cp.async.cg.shared.global [%0], [%1], 16;" :: "r"(dst), "l"(src))
#define CPCOMMIT()     asm volatile("cp.async.commit_group;" ::: "memory")
#define CPWAIT0()      asm volatile("cp.async.wait_group 0;" ::: "memory")

// split fp32 -> bf16 hi + bf16 residual(lo)
__device__ __forceinline__ void split2(float x0, float x1, uint32_t& hi, uint32_t& lo) {
    __nv_bfloat16 b0 = __float2bfloat16(x0), b1 = __float2bfloat16(x1);
    hi = (uint32_t)__bfloat16_as_ushort(b0) | ((uint32_t)__bfloat16_as_ushort(b1) << 16);
    lo = pkbf(x0 - __bfloat162float(b0), x1 - __bfloat162float(b1));
}

// ---------------- preprocessing: K/V fp32 -> swizzled bf16 hi/lo tiles (+mask detect) ----------------
__global__ void preconvert_kernel(const float* __restrict__ K, const float* __restrict__ V,
                                  const unsigned* __restrict__ mw) {
    const int ch = blockIdx.x, bh = blockIdx.y, t = threadIdx.x;   // 256 threads
    if (ch == 0 && bh == 0) {   // fold mask-kind detection into this launch
        __shared__ int s_i32bad, s_f32bad;
        if (t == 0) { s_i32bad = 0; s_f32bad = 0; }
        __syncthreads();
        for (int i = t; i < 1024; i += 256) {
            unsigned w = mw[i];
            if (w > 1u)                      atomicOr(&s_i32bad, 1);
            if (w != 0u && w != 0x3F800000u) atomicOr(&s_f32bad, 1);
        }
        __syncthreads();
        if (t == 0) g_mask_wide = (!s_i32bad || !s_f32bad) ? 1 : 0;
    }
    const float* ks = K + ((size_t)bh * S_LEN + ch * NKC) * DKD;
    const float* vs = V + ((size_t)bh * S_LEN + ch * NKC) * DKD;
    unsigned char* dst = g_kv16 + ((size_t)bh * NCH + ch) * CHUNK_B;
#pragma unroll
    for (int it = 0; it < 2; ++it) {
        int i = t + it * 256;           // 8-float group 0..511
        int row = i >> 3, c8 = i & 7;
        uint32_t o = SWZ((uint32_t)(row * 128 + c8 * 16));
        float4 a = *(const float4*)(ks + row * DKD + c8 * 8);
        float4 b = *(const float4*)(ks + row * DKD + c8 * 8 + 4);
        uint4 H, L;
        split2(a.x, a.y, H.x, L.x); split2(a.z, a.w, H.y, L.y);
        split2(b.x, b.y, H.z, L.z); split2(b.z, b.w, H.w, L.w);
        *(uint4*)(dst + o)          = H;
        *(uint4*)(dst + TILE_B + o) = L;
        a = *(const float4*)(vs + row * DKD + c8 * 8);
        b = *(const float4*)(vs + row * DKD + c8 * 8 + 4);
        split2(a.x, a.y, H.x, L.x); split2(a.z, a.w, H.y, L.y);
        split2(b.x, b.y, H.z, L.z); split2(b.z, b.w, H.w, L.w);
        *(uint4*)(dst + 2 * TILE_B + o) = H;
        *(uint4*)(dst + 3 * TILE_B + o) = L;
    }
}

// copy 16*n16 bytes from scratch gmem -> smem buffer
__device__ __forceinline__ void dma_tiles(uint32_t dst, const unsigned char* src, int t, int n16) {
#pragma unroll
    for (int kk = 0; kk < 8; ++kk) {
        if (kk * THREADS >= n16) break;
        int i = t + kk * THREADS;
        CP16(dst + i * 16, src + (size_t)i * 16);
    }
    CPCOMMIT();
}

// S phase with precomputed swizzled offsets: 4 j-frags, 12 mma each
__device__ __forceinline__ void s_phase_res(uint32_t khi, uint32_t klo,
                                            const uint32_t soff[4][2],
                                            const uint32_t QAh[4][4], const uint32_t QAl[4][4],
                                            float acc[4][4]) {
#pragma unroll
    for (int j = 0; j < 4; ++j) {
        uint32_t o0 = soff[j][0], o1 = soff[j][1];
        uint32_t h0, h1, h2, h3, l0, l1, l2, l3;
        ldsm4(khi + o0, h0, h1, h2, h3);
        mma16816(acc[j], QAh[0], h0, h1);
        mma16816(acc[j], QAh[1], h2, h3);
        mma16816(acc[j], QAl[0], h0, h1);
        mma16816(acc[j], QAl[1], h2, h3);
        ldsm4(klo + o0, l0, l1, l2, l3);
        mma16816(acc[j], QAh[0], l0, l1);
        mma16816(acc[j], QAh[1], l2, l3);
        ldsm4(khi + o1, h0, h1, h2, h3);
        mma16816(acc[j], QAh[2], h0, h1);
        mma16816(acc[j], QAh[3], h2, h3);
        mma16816(acc[j], QAl[2], h0, h1);
        mma16816(acc[j], QAl[3], h2, h3);
        ldsm4(klo + o1, l0, l1, l2, l3);
        mma16816(acc[j], QAh[2], l0, l1);
        mma16816(acc[j], QAh[3], l2, l3);
    }
}

__global__ void __launch_bounds__(THREADS, 2)
sdpa_mma_kernel(const float* __restrict__ Qg,
                const unsigned char* __restrict__ Mg,
                float* __restrict__ ctx_out,
                float* __restrict__ w_out)
{
    extern __shared__ char smem[];
    const uint32_t sb = smem_u32(smem);

    const int t    = threadIdx.x;
    const int lane = t & 31;
    const int w    = t >> 5;       // 0..7
    const int wr   = w & 3;        // warp-row: q rows wr*16..+15 (of 64)
    const int wc   = w >> 2;       // warp-col: k half 0/1 (32 cols of 64)
    const int tq   = lane >> 2;    // 0..7
    const int tc   = lane & 3;     // 0..3

    const int bh = blockIdx.y;
    const int qt = blockIdx.x;
    const int q0 = qt * MQT;
    const size_t row0 = (size_t)bh * S_LEN + q0;
    const int wide = g_mask_wide;

    float*  red  = (float*)(smem + O_RED);
    float*  sinv = (float*)(smem + O_INV);
    __half* ps   = (__half*)(smem + O_QS);   // p-staging tile (after Q frags loaded)

    const unsigned char* kvsrc = g_kv16 + (size_t)bh * NCH * CHUNK_B;

    const size_t qrA = row0 + wr * 16 + tq;
    const size_t qrB = qrA + 8;
    const size_t mrowA = qrA * (size_t)S_LEN;
    const size_t mrowB = qrB * (size_t)S_LEN;

    // local p-tile rows for this thread's frags
    const int prA = wr * 16 + tq;
    const int prB = prA + 8;

    // ---- precomputed swizzled ldsm offsets (chunk-invariant) ----
    uint32_t soff[4][2], voff[2][4];
#pragma unroll
    for (int j = 0; j < 4; ++j) {
        uint32_t base = (uint32_t)((wc * 32 + j * 8 + (lane & 7)) * 128 + (lane >> 3) * 16);
        soff[j][0] = SWZ(base);
        soff[j][1] = SWZ(base + 64);
    }
#pragma unroll
    for (int s = 0; s < 2; ++s)
#pragma unroll
        for (int j2 = 0; j2 < 4; ++j2)
            voff[s][j2] = SWZ((uint32_t)((wc * 32 + s * 16 + (lane & 15)) * 128
                                         + j2 * 32 + (lane >> 4) * 16));

    // ---- stage Q (scaled) into swizzled tiles ----
    {
        const float* qs = Qg + row0 * DKD;
#pragma unroll
        for (int it = 0; it < 2; ++it) {
            int i = t + it * THREADS;        // 8-float group 0..511
            int row = i >> 3, c8 = i & 7;
            uint32_t o = SWZ((uint32_t)(row * 128 + c8 * 16));
            float4 a = *(const float4*)(qs + row * DKD + c8 * 8);
            float4 b = *(const float4*)(qs + row * DKD + c8 * 8 + 4);
            a.x *= QSCALE; a.y *= QSCALE; a.z *= QSCALE; a.w *= QSCALE;
            b.x *= QSCALE; b.y *= QSCALE; b.z *= QSCALE; b.w *= QSCALE;
            uint4 H, L;
            split2(a.x, a.y, H.x, L.x); split2(a.z, a.w, H.y, L.y);
            split2(b.x, b.y, H.z, L.z); split2(b.z, b.w, H.w, L.w);
            *(uint4*)(smem + O_QS + o)           = H;
            *(uint4*)(smem + O_QS + QTILE_B + o) = L;
        }
    }
    __syncthreads();

    // ---- Q A-frags resident for entire kernel ----
    uint32_t QAh[4][4], QAl[4][4];
#pragma unroll
    for (int s = 0; s < 4; ++s) {
        uint32_t off = SWZ((uint32_t)((wr * 16 + (lane & 15)) * 128 + s * 32 + (lane >> 4) * 16));
        ldsm4(sb + O_QS + off,           QAh[s][0], QAh[s][1], QAh[s][2], QAh[s][3]);
        ldsm4(sb + O_QS + QTILE_B + off, QAl[s][0], QAl[s][1], QAl[s][2], QAl[s][3]);
    }
    __syncthreads();   // frags loaded; O_QS region becomes the p-staging tile

    // ---- prologue prefetch chunk0 -> buf0 ----
    dma_tiles(sb + O_BUF0, kvsrc, t, CHUNK_B / 16);

    float ctx[8][4] = {};
    float rs0 = 0.f, rs1 = 0.f;

    // ================== PASS 1: S + exp + rowsum + p staging + PV ==================
    for (int ch = 0; ch < NCH; ++ch) {
        const int kb = ch * NKC;
        const uint32_t buf = sb + ((ch & 1) ? O_BUF1 : O_BUF0);

        // mask gather FIRST: LDGs fly while the DMA drains
        uint32_t mk = 0;
#pragma unroll
        for (int j = 0; j < 4; ++j) {
            int col = kb + wc * 32 + j * 8 + 2 * tc;
            uint32_t b0, b1, b2, b3;
            if (wide) {
                uint2 a = *(const uint2*)((const unsigned*)Mg + mrowA + col);
                uint2 b = *(const uint2*)((const unsigned*)Mg + mrowB + col);
                b0 = a.x != 0u; b1 = a.y != 0u; b2 = b.x != 0u; b3 = b.y != 0u;
            } else {
                unsigned short a = *(const unsigned short*)(Mg + mrowA + col);
                unsigned short b = *(const unsigned short*)(Mg + mrowB + col);
                b0 = (a & 0xFF) != 0; b1 = (a >> 8) != 0;
                b2 = (b & 0xFF) != 0; b3 = (b >> 8) != 0;
            }
            mk |= (b0 << (4 * j)) | (b1 << (4 * j + 1)) | (b2 << (4 * j + 2)) | (b3 << (4 * j + 3));
        }

        CPWAIT0();
        __syncthreads();   // chunk ready; prev coop-store reads of ps done (barrier last iter)
        if (ch + 1 < NCH)
            dma_tiles(sb + ((ch & 1) ? O_BUF0 : O_BUF1),
                      kvsrc + (size_t)(ch + 1) * CHUNK_B, t, CHUNK_B / 16);

        // S phase
        float acc[4][4] = {};
        s_phase_res(buf, buf + TILE_B, soff, QAh, QAl, acc);

        // mask + exp2 + rowsum + p staging into padded smem tile (conflict-free half2 STS)
#pragma unroll
        for (int j = 0; j < 4; ++j) {
            float e0 = ((mk >> (4 * j)) & 1u)     ? 0.f : ex2f(acc[j][0]);
            float e1 = ((mk >> (4 * j + 1)) & 1u) ? 0.f : ex2f(acc[j][1]);
            float e2 = ((mk >> (4 * j + 2)) & 1u) ? 0.f : ex2f(acc[j][2]);
            float e3 = ((mk >> (4 * j + 3)) & 1u) ? 0.f : ex2f(acc[j][3]);
            rs0 += e0 + e1;  rs1 += e2 + e3;
            int col = wc * 32 + j * 8 + 2 * tc;
            *(__half2*)(ps + prA * PS_STR + col) = __floats2half2_rn(e0, e1);
            *(__half2*)(ps + prB * PS_STR + col) = __floats2half2_rn(e2, e3);
            acc[j][0] = e0; acc[j][1] = e1; acc[j][2] = e2; acc[j][3] = e3;
        }

        // repack P as bf16 hi/lo A-frags (2 k16 frags over this warp's 32 k)
        uint32_t PAh[2][4], PAl[2][4];
#pragma unroll
        for (int s = 0; s < 2; ++s) {
            split2(acc[2 * s][0],     acc[2 * s][1],     PAh[s][0], PAl[s][0]);
            split2(acc[2 * s][2],     acc[2 * s][3],     PAh[s][1], PAl[s][1]);
            split2(acc[2 * s + 1][0], acc[2 * s + 1][1], PAh[s][2], PAl[s][2]);
            split2(acc[2 * s + 1][2], acc[2 * s + 1][3], PAh[s][3], PAl[s][3]);
        }

        // PV phase: V rows wc*32..+31
        const uint32_t vhi = buf + 2 * TILE_B, vlo = buf + 3 * TILE_B;
#pragma unroll
        for (int s = 0; s < 2; ++s) {
#pragma unroll
            for (int j2 = 0; j2 < 4; ++j2) {
                uint32_t o = voff[s][j2];
                uint32_t bh0, bh1, bh2, bh3, bl0, bl1, bl2, bl3;
                ldsm4t(vhi + o, bh0, bh1, bh2, bh3);
                ldsm4t(vlo + o, bl0, bl1, bl2, bl3);
                mma16816(ctx[2 * j2],     PAh[s], bh0, bh1);
                mma16816(ctx[2 * j2],     PAl[s], bh0, bh1);
                mma16816(ctx[2 * j2],     PAh[s], bl0, bl1);
                mma16816(ctx[2 * j2 + 1], PAh[s], bh2, bh3);
                mma16816(ctx[2 * j2 + 1], PAl[s], bh2, bh3);
                mma16816(ctx[2 * j2 + 1], PAh[s], bl2, bl3);
            }
        }

        __syncthreads();   // p tile complete

        // coop coalesced fp16 store: thread -> row t/4, 16 halves at col (t%4)*16
        {
            int r = t >> 2, cb = (t & 3) * 16;
            const uint4* srcp = (const uint4*)(ps + r * PS_STR + cb);
            uint4 a = srcp[0], b = srcp[1];
            uint4* dstp = (uint4*)(g_pstage + (row0 + r) * (size_t)S_LEN + kb + cb);
            __stcs(dstp,     a);
            __stcs(dstp + 1, b);
        }
        // ps reuse protected by the barrier at the top of the next iteration
    }

    // ================= row-sum reduction =================
    __syncthreads();
    if (t < 64) red[t] = 0.f;
    __syncthreads();
    rs0 += __shfl_xor_sync(0xffffffffu, rs0, 1);
    rs0 += __shfl_xor_sync(0xffffffffu, rs0, 2);
    rs1 += __shfl_xor_sync(0xffffffffu, rs1, 1);
    rs1 += __shfl_xor_sync(0xffffffffu, rs1, 2);
    if (tc == 0) {
        atomicAdd(&red[wr * 16 + tq], rs0);
        atomicAdd(&red[wr * 16 + tq + 8], rs1);
    }
    // ctx partials into buf1: 2 groups x 64x64 fp32
    {
        float* cbuf = (float*)(smem + O_BUF1) + wc * 4096;
#pragma unroll
        for (int j = 0; j < 8; ++j) {
            int row = wr * 16 + tq, col = j * 8 + 2 * tc;
            *(float2*)(cbuf + row * 64 + col)       = make_float2(ctx[j][0], ctx[j][1]);
            *(float2*)(cbuf + (row + 8) * 64 + col) = make_float2(ctx[j][2], ctx[j][3]);
        }
    }
    __syncthreads();
    if (t < 64) sinv[t] = 1.0f / red[t];
    __syncthreads();

    // ================= ctx combine (2 groups) + write =================
    {
        const float4* b0 = (const float4*)(smem + O_BUF1);
#pragma unroll
        for (int kk = 0; kk < 4; ++kk) {
            int i = t + kk * THREADS;       // float4 idx 0..1023
            int row = i >> 4, c4 = i & 15;
            float4 a = b0[i], b = b0[i + 1024];
            float iv = sinv[row];
            float4 o;
            o.x = (a.x + b.x) * iv;
            o.y = (a.y + b.y) * iv;
            o.z = (a.z + b.z) * iv;
            o.w = (a.w + b.w) * iv;
            *(float4*)(ctx_out + (row0 + row) * DKD + c4 * 4) = o;
        }
    }

    // ================== TAIL: normalize fp16 p -> fp32 weights (coalesced) ==================
#pragma unroll 2
    for (int r = 0; r < MQT; ++r) {
        const float iv = sinv[r];
        const __half2* src = (const __half2*)(g_pstage + (row0 + r) * (size_t)S_LEN) + t * 4;
        float* dst = w_out + (row0 + r) * (size_t)S_LEN + t * 8;
        uint4 raw = *(const uint4*)src;               // 8 halves
        __half2 h0 = *(__half2*)&raw.x, h1 = *(__half2*)&raw.y;
        __half2 h2 = *(__half2*)&raw.z, h3 = *(__half2*)&raw.w;
        float2 f0 = __half22float2(h0), f1 = __half22float2(h1);
        float2 f2 = __half22float2(h2), f3 = __half22float2(h3);
        float4 oA = make_float4(f0.x * iv, f0.y * iv, f1.x * iv, f1.y * iv);
        float4 oB = make_float4(f2.x * iv, f2.y * iv, f3.x * iv, f3.y * iv);
        __stcs((float4*)dst,       oA);
        __stcs((float4*)(dst + 4), oB);
    }
}

extern "C" void kernel_launch(void* const* d_in, const int* in_sizes, int n_in,
                              void* d_out, int out_size)
{
    const float*         Q = (const float*)d_in[0];
    const float*         K = (const float*)d_in[1];
    const float*         V = (const float*)d_in[2];
    const unsigned char* M = (const unsigned char*)d_in[3];

    float* ctx = (float*)d_out;
    float* wts = (float*)d_out + (size_t)BHN * S_LEN * DKD;

    cudaFuncSetAttribute(sdpa_mma_kernel,
                         cudaFuncAttributeMaxDynamicSharedMemorySize, SMEMB);

    preconvert_kernel<<<dim3(NCH, BHN), 256>>>(K, V, (const unsigned*)M);

    dim3 grid(NQT, BHN);   // (32, 32) = 1024 CTAs, 2 resident per SM
    sdpa_mma_kernel<<<grid, THREADS, SMEMB>>>(Q, M, ctx, wts);
}

// round 15
// speedup vs baseline: 1.0528x; 1.0528x over previous
#include <cuda_runtime.h>
#include <cuda_bf16.h>
#include <cstdint>
#include <cstddef>

#define S_LEN   2048
#define DKD     64
#define BHN     32
#define MQT     32           // q rows per CTA
#define NKC     64           // k cols per chunk
#define NCH     (S_LEN / NKC)   // 32
#define NQT     (S_LEN / MQT)   // 64
#define THREADS 256

// 0.125 * log2(e): fold softmax scale + exp->exp2 conversion into Q
#define QSCALE 0.1803368801111831f

#define TILE_B  8192         // one 64x64 bf16 K/V tile, SW128 swizzled, 128B rows
#define CHUNK_B 32768        // Khi,Klo,Vhi,Vlo per chunk
#define QTILE_B 4096         // 32x64 bf16 Q tile

// ---- smem byte offsets ----
#define O_BUF0 0
#define O_BUF1 32768
#define O_MC   65536         // Q staging (8KB) at startup; mask cache (16KB) afterwards
#define O_RED  81920         // 32 floats
#define O_INV  82176         // 32 floats
#define SMEMB  82432

#define SWZ(o) ((o) ^ (((o) >> 3) & 0x70))

// bf16 hi/lo K,V tiles, pre-swizzled ldmatrix-ready images (32 MB scratch)
__device__ __align__(16) unsigned char g_kv16[(size_t)BHN * NCH * CHUNK_B];
__device__ int g_mask_wide;

// ---------------- helpers ----------------
__device__ __forceinline__ uint32_t smem_u32(const void* p) {
    uint32_t a;
    asm("{ .reg .u64 t; cvta.to.shared.u64 t, %1; cvt.u32.u64 %0, t; }" : "=r"(a) : "l"(p));
    return a;
}
__device__ __forceinline__ float ex2f(float x) {
    float y; asm("ex2.approx.f32 %0, %1;" : "=f"(y) : "f"(x)); return y;
}
__device__ __forceinline__ uint32_t pkbf(float lo, float hi) {  // lo -> bits[15:0]
    uint32_t r; asm("cvt.rn.bf16x2.f32 %0, %1, %2;" : "=r"(r) : "f"(hi), "f"(lo)); return r;
}
__device__ __forceinline__ void ldsm4(uint32_t a, uint32_t& r0, uint32_t& r1, uint32_t& r2, uint32_t& r3) {
    asm volatile("ldmatrix.sync.aligned.m8n8.x4.shared.b16 {%0,%1,%2,%3}, [%4];"
                 : "=r"(r0), "=r"(r1), "=r"(r2), "=r"(r3) : "r"(a));
}
__device__ __forceinline__ void ldsm4t(uint32_t a, uint32_t& r0, uint32_t& r1, uint32_t& r2, uint32_t& r3) {
    asm volatile("ldmatrix.sync.aligned.m8n8.x4.trans.shared.b16 {%0,%1,%2,%3}, [%4];"
                 : "=r"(r0), "=r"(r1), "=r"(r2), "=r"(r3) : "r"(a));
}
__device__ __forceinline__ void mma16816(float* c, const uint32_t* A, uint32_t b0, uint32_t b1) {
    asm volatile("mma.sync.aligned.m16n8k16.row.col.f32.bf16.bf16.f32 "
                 "{%0,%1,%2,%3}, {%4,%5,%6,%7}, {%8,%9}, {%0,%1,%2,%3};"
                 : "+f"(c[0]), "+f"(c[1]), "+f"(c[2]), "+f"(c[3])
                 : "r"(A[0]), "r"(A[1]), "r"(A[2]), "r"(A[3]), "r"(b0), "r"(b1));
}
#define CP16(dst, src) asm volatile("cp.async.cg.shared.global [%0], [%1], 16;" :: "r"(dst), "l"(src))
#define CPCOMMIT()     asm volatile("cp.async.commit_group;" ::: "memory")
#define CPWAIT0()      asm volatile("cp.async.wait_group 0;" ::: "memory")

// split fp32 -> bf16 hi + bf16 residual(lo)
__device__ __forceinline__ void split2(float x0, float x1, uint32_t& hi, uint32_t& lo) {
    __nv_bfloat16 b0 = __float2bfloat16(x0), b1 = __float2bfloat16(x1);
    hi = (uint32_t)__bfloat16_as_ushort(b0) | ((uint32_t)__bfloat16_as_ushort(b1) << 16);
    lo = pkbf(x0 - __bfloat162float(b0), x1 - __bfloat162float(b1));
}

// ---------------- preprocessing: K/V fp32 -> swizzled bf16 hi/lo tiles (+mask detect) ----------------
__global__ void preconvert_kernel(const float* __restrict__ K, const float* __restrict__ V,
                                  const unsigned* __restrict__ mw) {
    const int ch = blockIdx.x, bh = blockIdx.y, t = threadIdx.x;   // 256 threads
    if (ch == 0 && bh == 0) {
        __shared__ int s_i32bad, s_f32bad;
        if (t == 0) { s_i32bad = 0; s_f32bad = 0; }
        __syncthreads();
        for (int i = t; i < 1024; i += 256) {
            unsigned w = mw[i];
            if (w > 1u)                      atomicOr(&s_i32bad, 1);
            if (w != 0u && w != 0x3F800000u) atomicOr(&s_f32bad, 1);
        }
        __syncthreads();
        if (t == 0) g_mask_wide = (!s_i32bad || !s_f32bad) ? 1 : 0;
    }
    const float* ks = K + ((size_t)bh * S_LEN + ch * NKC) * DKD;
    const float* vs = V + ((size_t)bh * S_LEN + ch * NKC) * DKD;
    unsigned char* dst = g_kv16 + ((size_t)bh * NCH + ch) * CHUNK_B;
#pragma unroll
    for (int it = 0; it < 2; ++it) {
        int i = t + it * 256;           // 8-float group 0..511
        int row = i >> 3, c8 = i & 7;
        uint32_t o = SWZ((uint32_t)(row * 128 + c8 * 16));
        float4 a = *(const float4*)(ks + row * DKD + c8 * 8);
        float4 b = *(const float4*)(ks + row * DKD + c8 * 8 + 4);
        uint4 H, L;
        split2(a.x, a.y, H.x, L.x); split2(a.z, a.w, H.y, L.y);
        split2(b.x, b.y, H.z, L.z); split2(b.z, b.w, H.w, L.w);
        *(uint4*)(dst + o)          = H;
        *(uint4*)(dst + TILE_B + o) = L;
        a = *(const float4*)(vs + row * DKD + c8 * 8);
        b = *(const float4*)(vs + row * DKD + c8 * 8 + 4);
        split2(a.x, a.y, H.x, L.x); split2(a.z, a.w, H.y, L.y);
        split2(b.x, b.y, H.z, L.z); split2(b.z, b.w, H.w, L.w);
        *(uint4*)(dst + 2 * TILE_B + o) = H;
        *(uint4*)(dst + 3 * TILE_B + o) = L;
    }
}

// copy 16*n16 bytes from scratch gmem -> smem buffer
__device__ __forceinline__ void dma_tiles(uint32_t dst, const unsigned char* src, int t, int n16) {
#pragma unroll
    for (int kk = 0; kk < 8; ++kk) {
        if (kk * THREADS >= n16) break;
        int i = t + kk * THREADS;
        CP16(dst + i * 16, src + (size_t)i * 16);
    }
    CPCOMMIT();
}

// S phase (warp covers 16 q x 16 k): 2 j-frags, 12 mma each
__device__ __forceinline__ void s_phase_res(uint32_t khi, uint32_t klo,
                                            const uint32_t soff[2][2],
                                            const uint32_t QAh[4][4], const uint32_t QAl[4][4],
                                            float acc[2][4]) {
#pragma unroll
    for (int j = 0; j < 2; ++j) {
        uint32_t o0 = soff[j][0], o1 = soff[j][1];
        uint32_t h0, h1, h2, h3, l0, l1, l2, l3;
        ldsm4(khi + o0, h0, h1, h2, h3);
        mma16816(acc[j], QAh[0], h0, h1);
        mma16816(acc[j], QAh[1], h2, h3);
        mma16816(acc[j], QAl[0], h0, h1);
        mma16816(acc[j], QAl[1], h2, h3);
        ldsm4(klo + o0, l0, l1, l2, l3);
        mma16816(acc[j], QAh[0], l0, l1);
        mma16816(acc[j], QAh[1], l2, l3);
        ldsm4(khi + o1, h0, h1, h2, h3);
        mma16816(acc[j], QAh[2], h0, h1);
        mma16816(acc[j], QAh[3], h2, h3);
        mma16816(acc[j], QAl[2], h0, h1);
        mma16816(acc[j], QAl[3], h2, h3);
        ldsm4(klo + o1, l0, l1, l2, l3);
        mma16816(acc[j], QAh[2], l0, l1);
        mma16816(acc[j], QAh[3], l2, l3);
    }
}

__global__ void __launch_bounds__(THREADS, 2)
sdpa_mma_kernel(const float* __restrict__ Qg,
                const unsigned char* __restrict__ Mg,
                float* __restrict__ ctx_out,
                float* __restrict__ w_out)
{
    extern __shared__ char smem[];
    const uint32_t sb = smem_u32(smem);

    const int t    = threadIdx.x;
    const int lane = t & 31;
    const int w    = t >> 5;       // 0..7
    const int wr   = w & 1;        // warp-row: q rows wr*16..+15 (of 32)
    const int wc   = w >> 1;       // warp-col: k quarter 0..3 (16 cols of 64)
    const int tq   = lane >> 2;    // 0..7
    const int tc   = lane & 3;     // 0..3

    const int bh = blockIdx.y;
    const int qt = blockIdx.x;
    const int q0 = qt * MQT;
    const size_t row0 = (size_t)bh * S_LEN + q0;
    const int wide = g_mask_wide;

    float*          red    = (float*)(smem + O_RED);
    float*          sinv   = (float*)(smem + O_INV);
    unsigned short* mcache = (unsigned short*)(smem + O_MC);

    const unsigned char* kvsrc = g_kv16 + (size_t)bh * NCH * CHUNK_B;

    const size_t qrA = row0 + wr * 16 + tq;
    const size_t qrB = qrA + 8;
    const size_t mrowA = qrA * (size_t)S_LEN;
    const size_t mrowB = qrB * (size_t)S_LEN;

    // ---- precomputed swizzled ldsm offsets (chunk-invariant) ----
    uint32_t soff[2][2], voff[4];
#pragma unroll
    for (int j = 0; j < 2; ++j) {
        uint32_t base = (uint32_t)((wc * 16 + j * 8 + (lane & 7)) * 128 + (lane >> 3) * 16);
        soff[j][0] = SWZ(base);
        soff[j][1] = SWZ(base + 64);
    }
#pragma unroll
    for (int j2 = 0; j2 < 4; ++j2)
        voff[j2] = SWZ((uint32_t)((wc * 16 + (lane & 15)) * 128 + j2 * 32 + (lane >> 4) * 16));

    // ---- stage Q (scaled) into swizzled tiles in the mcache region ----
    {
        const float* qs = Qg + row0 * DKD;
        int i = t;                        // 8-float group 0..255 (32 rows x 8)
        int row = i >> 3, c8 = i & 7;
        uint32_t o = SWZ((uint32_t)(row * 128 + c8 * 16));
        float4 a = *(const float4*)(qs + row * DKD + c8 * 8);
        float4 b = *(const float4*)(qs + row * DKD + c8 * 8 + 4);
        a.x *= QSCALE; a.y *= QSCALE; a.z *= QSCALE; a.w *= QSCALE;
        b.x *= QSCALE; b.y *= QSCALE; b.z *= QSCALE; b.w *= QSCALE;
        uint4 H, L;
        split2(a.x, a.y, H.x, L.x); split2(a.z, a.w, H.y, L.y);
        split2(b.x, b.y, H.z, L.z); split2(b.z, b.w, H.w, L.w);
        *(uint4*)(smem + O_MC + o)           = H;
        *(uint4*)(smem + O_MC + QTILE_B + o) = L;
    }
    __syncthreads();

    // ---- Q A-frags resident for entire kernel ----
    uint32_t QAh[4][4], QAl[4][4];
#pragma unroll
    for (int s = 0; s < 4; ++s) {
        uint32_t off = SWZ((uint32_t)((wr * 16 + (lane & 15)) * 128 + s * 32 + (lane >> 4) * 16));
        ldsm4(sb + O_MC + off,           QAh[s][0], QAh[s][1], QAh[s][2], QAh[s][3]);
        ldsm4(sb + O_MC + QTILE_B + off, QAl[s][0], QAl[s][1], QAl[s][2], QAl[s][3]);
    }
    __syncthreads();   // frags loaded; mcache region reusable as mask cache

    // ---- prologue prefetch chunk0 -> buf0 ----
    dma_tiles(sb + O_BUF0, kvsrc, t, CHUNK_B / 16);

    float ctx[8][4] = {};
    float rs0 = 0.f, rs1 = 0.f;

    // ================== PASS 1: S + exp + rowsum + PV ==================
    for (int ch = 0; ch < NCH; ++ch) {
        const int kb = ch * NKC;
        const uint32_t buf = sb + ((ch & 1) ? O_BUF1 : O_BUF0);

        // mask gather FIRST: LDGs fly while the DMA drains
        uint32_t mk = 0;
#pragma unroll
        for (int j = 0; j < 2; ++j) {
            int col = kb + wc * 16 + j * 8 + 2 * tc;
            uint32_t b0, b1, b2, b3;
            if (wide) {
                uint2 a = *(const uint2*)((const unsigned*)Mg + mrowA + col);
                uint2 b = *(const uint2*)((const unsigned*)Mg + mrowB + col);
                b0 = a.x != 0u; b1 = a.y != 0u; b2 = b.x != 0u; b3 = b.y != 0u;
            } else {
                unsigned short a = *(const unsigned short*)(Mg + mrowA + col);
                unsigned short b = *(const unsigned short*)(Mg + mrowB + col);
                b0 = (a & 0xFF) != 0; b1 = (a >> 8) != 0;
                b2 = (b & 0xFF) != 0; b3 = (b >> 8) != 0;
            }
            mk |= (b0 << (4 * j)) | (b1 << (4 * j + 1)) | (b2 << (4 * j + 2)) | (b3 << (4 * j + 3));
        }

        CPWAIT0();
        __syncthreads();   // chunk ch ready; prev compute done everywhere
        if (ch + 1 < NCH)
            dma_tiles(sb + ((ch & 1) ? O_BUF0 : O_BUF1),
                      kvsrc + (size_t)(ch + 1) * CHUNK_B, t, CHUNK_B / 16);

        mcache[ch * THREADS + t] = (unsigned short)mk;

        // S phase
        float acc[2][4] = {};
        s_phase_res(buf, buf + TILE_B, soff, QAh, QAl, acc);

        // mask + exp2 + rowsum
#pragma unroll
        for (int j = 0; j < 2; ++j) {
            float e0 = ((mk >> (4 * j)) & 1u)     ? 0.f : ex2f(acc[j][0]);
            float e1 = ((mk >> (4 * j + 1)) & 1u) ? 0.f : ex2f(acc[j][1]);
            float e2 = ((mk >> (4 * j + 2)) & 1u) ? 0.f : ex2f(acc[j][2]);
            float e3 = ((mk >> (4 * j + 3)) & 1u) ? 0.f : ex2f(acc[j][3]);
            rs0 += e0 + e1;  rs1 += e2 + e3;
            acc[j][0] = e0; acc[j][1] = e1; acc[j][2] = e2; acc[j][3] = e3;
        }

        // repack P as bf16 hi/lo A-frags (one k16 frag over this warp's 16 k)
        uint32_t PAh[4], PAl[4];
        split2(acc[0][0], acc[0][1], PAh[0], PAl[0]);
        split2(acc[0][2], acc[0][3], PAh[1], PAl[1]);
        split2(acc[1][0], acc[1][1], PAh[2], PAl[2]);
        split2(acc[1][2], acc[1][3], PAh[3], PAl[3]);

        // PV phase: V rows wc*16..+15
        const uint32_t vhi = buf + 2 * TILE_B, vlo = buf + 3 * TILE_B;
#pragma unroll
        for (int j2 = 0; j2 < 4; ++j2) {
            uint32_t o = voff[j2];
            uint32_t bh0, bh1, bh2, bh3, bl0, bl1, bl2, bl3;
            ldsm4t(vhi + o, bh0, bh1, bh2, bh3);
            ldsm4t(vlo + o, bl0, bl1, bl2, bl3);
            mma16816(ctx[2 * j2],     PAh, bh0, bh1);
            mma16816(ctx[2 * j2],     PAl, bh0, bh1);
            mma16816(ctx[2 * j2],     PAh, bl0, bl1);
            mma16816(ctx[2 * j2 + 1], PAh, bh2, bh3);
            mma16816(ctx[2 * j2 + 1], PAl, bh2, bh3);
            mma16816(ctx[2 * j2 + 1], PAh, bl2, bl3);
        }
    }

    __syncthreads();   // everyone done with buffers
    // pass-2 prefetch: K tiles of chunk0 -> buf0 (16 KB)
    dma_tiles(sb + O_BUF0, kvsrc, t, 2 * TILE_B / 16);

    // ================= row-sum reduction =================
    if (t < 32) red[t] = 0.f;
    __syncthreads();
    rs0 += __shfl_xor_sync(0xffffffffu, rs0, 1);
    rs0 += __shfl_xor_sync(0xffffffffu, rs0, 2);
    rs1 += __shfl_xor_sync(0xffffffffu, rs1, 1);
    rs1 += __shfl_xor_sync(0xffffffffu, rs1, 2);
    if (tc == 0) {
        atomicAdd(&red[wr * 16 + tq], rs0);
        atomicAdd(&red[wr * 16 + tq + 8], rs1);
    }
    // ctx partials into buf1: 4 groups x 32x64 fp32 (8KB each)
    {
        float* cbuf = (float*)(smem + O_BUF1) + wc * 2048;
#pragma unroll
        for (int j = 0; j < 8; ++j) {
            int row = wr * 16 + tq, col = j * 8 + 2 * tc;
            *(float2*)(cbuf + row * 64 + col)       = make_float2(ctx[j][0], ctx[j][1]);
            *(float2*)(cbuf + (row + 8) * 64 + col) = make_float2(ctx[j][2], ctx[j][3]);
        }
    }
    __syncthreads();
    if (t < 32) sinv[t] = 1.0f / red[t];
    __syncthreads();

    // ================= ctx combine (4 groups) + write =================
    {
        const float4* b0 = (const float4*)(smem + O_BUF1);
#pragma unroll
        for (int kk = 0; kk < 2; ++kk) {
            int i = t + kk * THREADS;       // float4 idx 0..511
            int row = i >> 4, c4 = i & 15;
            float4 a = b0[i], b = b0[i + 512], c = b0[i + 1024], d = b0[i + 1536];
            float iv = sinv[row];
            float4 o;
            o.x = (a.x + b.x + c.x + d.x) * iv;
            o.y = (a.y + b.y + c.y + d.y) * iv;
            o.z = (a.z + b.z + c.z + d.z) * iv;
            o.w = (a.w + b.w + c.w + d.w) * iv;
            *(float4*)(ctx_out + (row0 + row) * DKD + c4 * 4) = o;
        }
    }
    __syncthreads();   // buf1 free again

    // ================== PASS 2: recompute S, write normalized weights ==================
    const float ivA = sinv[wr * 16 + tq];
    const float ivB = sinv[wr * 16 + tq + 8];
    for (int ch = 0; ch < NCH; ++ch) {
        const int kb = ch * NKC;
        const uint32_t buf = sb + ((ch & 1) ? O_BUF1 : O_BUF0);

        CPWAIT0();
        __syncthreads();
        if (ch + 1 < NCH)
            dma_tiles(sb + ((ch & 1) ? O_BUF0 : O_BUF1),
                      kvsrc + (size_t)(ch + 1) * CHUNK_B, t, 2 * TILE_B / 16);

        float acc[2][4] = {};
        s_phase_res(buf, buf + TILE_B, soff, QAh, QAl, acc);

        const uint32_t mk = mcache[ch * THREADS + t];
#pragma unroll
        for (int j = 0; j < 2; ++j) {
            float e0 = ((mk >> (4 * j)) & 1u)     ? 0.f : ex2f(acc[j][0]) * ivA;
            float e1 = ((mk >> (4 * j + 1)) & 1u) ? 0.f : ex2f(acc[j][1]) * ivA;
            float e2 = ((mk >> (4 * j + 2)) & 1u) ? 0.f : ex2f(acc[j][2]) * ivB;
            float e3 = ((mk >> (4 * j + 3)) & 1u) ? 0.f : ex2f(acc[j][3]) * ivB;
            int col = kb + wc * 16 + j * 8 + 2 * tc;
            __stcs((float2*)(w_out + mrowA + col), make_float2(e0, e1));
            __stcs((float2*)(w_out + mrowB + col), make_float2(e2, e3));
        }
    }
}

extern "C" void kernel_launch(void* const* d_in, const int* in_sizes, int n_in,
                              void* d_out, int out_size)
{
    const float*         Q = (const float*)d_in[0];
    const float*         K = (const float*)d_in[1];
    const float*         V = (const float*)d_in[2];
    const unsigned char* M = (const unsigned char*)d_in[3];

    float* ctx = (float*)d_out;
    float* wts = (float*)d_out + (size_t)BHN * S_LEN * DKD;

    cudaFuncSetAttribute(sdpa_mma_kernel,
                         cudaFuncAttributeMaxDynamicSharedMemorySize, SMEMB);

    preconvert_kernel<<<dim3(NCH, BHN), 256>>>(K, V, (const unsigned*)M);

    dim3 grid(NQT, BHN);   // (64, 32) = 2048 CTAs, 2 resident per SM
    sdpa_mma_kernel<<<grid, THREADS, SMEMB>>>(Q, M, ctx, wts);
}

// round 16
// speedup vs baseline: 1.5414x; 1.4641x over previous
#include <cuda_runtime.h>
#include <cuda_fp16.h>
#include <cstdint>
#include <cstddef>

#define S_LEN   2048
#define DKD     64
#define BHN     32
#define MQT     64           // q rows per CTA
#define NKC     64           // k cols per chunk
#define NCH     (S_LEN / NKC)   // 32
#define NQT     (S_LEN / MQT)   // 32
#define THREADS 256

// 0.125 * log2(e): fold softmax scale + exp->exp2 conversion into Q
#define QSCALE 0.1803368801111831f

#define TILE_B  8192         // one 64x64 fp16 tile, SW128 swizzled, 128B rows
#define CHUNK_B 16384        // Kh,Vh per chunk
#define QTILE_B 8192         // 64x64 fp16 Q tile

// ---- smem byte offsets ----
#define O_BUF0 0
#define O_BUF1 16384
#define O_MC   32768         // Q staging (16KB) at startup; mask cache (16KB) afterwards
#define O_RED  49152         // 64 floats
#define O_INV  49408         // 64 floats
#define SMEMB  49664

#define SWZ(o) ((o) ^ (((o) >> 3) & 0x70))

// fp16 K,V hi tiles, pre-swizzled ldmatrix-ready images (16 MB scratch)
__device__ __align__(16) unsigned char g_kv16[(size_t)BHN * NCH * CHUNK_B];
__device__ int g_mask_wide;

// ---------------- helpers ----------------
__device__ __forceinline__ uint32_t smem_u32(const void* p) {
    uint32_t a;
    asm("{ .reg .u64 t; cvta.to.shared.u64 t, %1; cvt.u32.u64 %0, t; }" : "=r"(a) : "l"(p));
    return a;
}
__device__ __forceinline__ float ex2f(float x) {
    float y; asm("ex2.approx.f32 %0, %1;" : "=f"(y) : "f"(x)); return y;
}
__device__ __forceinline__ void ldsm4(uint32_t a, uint32_t& r0, uint32_t& r1, uint32_t& r2, uint32_t& r3) {
    asm volatile("ldmatrix.sync.aligned.m8n8.x4.shared.b16 {%0,%1,%2,%3}, [%4];"
                 : "=r"(r0), "=r"(r1), "=r"(r2), "=r"(r3) : "r"(a));
}
__device__ __forceinline__ void ldsm4t(uint32_t a, uint32_t& r0, uint32_t& r1, uint32_t& r2, uint32_t& r3) {
    asm volatile("ldmatrix.sync.aligned.m8n8.x4.trans.shared.b16 {%0,%1,%2,%3}, [%4];"
                 : "=r"(r0), "=r"(r1), "=r"(r2), "=r"(r3) : "r"(a));
}
// fp16 x fp16 -> fp32 accum
__device__ __forceinline__ void mma16816(float* c, const uint32_t* A, uint32_t b0, uint32_t b1) {
    asm volatile("mma.sync.aligned.m16n8k16.row.col.f32.f16.f16.f32 "
                 "{%0,%1,%2,%3}, {%4,%5,%6,%7}, {%8,%9}, {%0,%1,%2,%3};"
                 : "+f"(c[0]), "+f"(c[1]), "+f"(c[2]), "+f"(c[3])
                 : "r"(A[0]), "r"(A[1]), "r"(A[2]), "r"(A[3]), "r"(b0), "r"(b1));
}
#define CP16(dst, src) asm volatile("cp.async.cg.shared.global [%0], [%1], 16;" :: "r"(dst), "l"(src))
#define CPCOMMIT()     asm volatile("cp.async.commit_group;" ::: "memory")
#define CPWAIT0()      asm volatile("cp.async.wait_group 0;" ::: "memory")

// split fp32 pair -> fp16 hi pair + fp16 residual(lo) pair
__device__ __forceinline__ void splitH(float x0, float x1, uint32_t& hi, uint32_t& lo) {
    __half h0 = __float2half_rn(x0), h1 = __float2half_rn(x1);
    __half2 hp = __halves2half2(h0, h1);
    hi = *(uint32_t*)&hp;
    __half2 lp = __floats2half2_rn(x0 - __half2float(h0), x1 - __half2float(h1));
    lo = *(uint32_t*)&lp;
}
// fp16 hi only (for K/V preconvert)
__device__ __forceinline__ uint32_t cvtH(float x0, float x1) {
    __half2 hp = __floats2half2_rn(x0, x1);
    return *(uint32_t*)&hp;
}

// ---------------- preprocessing: K/V fp32 -> swizzled fp16 tiles (+mask detect) ----------------
__global__ void preconvert_kernel(const float* __restrict__ K, const float* __restrict__ V,
                                  const unsigned* __restrict__ mw) {
    const int ch = blockIdx.x, bh = blockIdx.y, t = threadIdx.x;   // 256 threads
    if (ch == 0 && bh == 0) {
        __shared__ int s_i32bad, s_f32bad;
        if (t == 0) { s_i32bad = 0; s_f32bad = 0; }
        __syncthreads();
        for (int i = t; i < 1024; i += 256) {
            unsigned w = mw[i];
            if (w > 1u)                      atomicOr(&s_i32bad, 1);
            if (w != 0u && w != 0x3F800000u) atomicOr(&s_f32bad, 1);
        }
        __syncthreads();
        if (t == 0) g_mask_wide = (!s_i32bad || !s_f32bad) ? 1 : 0;
    }
    const float* ks = K + ((size_t)bh * S_LEN + ch * NKC) * DKD;
    const float* vs = V + ((size_t)bh * S_LEN + ch * NKC) * DKD;
    unsigned char* dst = g_kv16 + ((size_t)bh * NCH + ch) * CHUNK_B;
#pragma unroll
    for (int it = 0; it < 2; ++it) {
        int i = t + it * 256;           // 8-float group 0..511
        int row = i >> 3, c8 = i & 7;
        uint32_t o = SWZ((uint32_t)(row * 128 + c8 * 16));
        float4 a = *(const float4*)(ks + row * DKD + c8 * 8);
        float4 b = *(const float4*)(ks + row * DKD + c8 * 8 + 4);
        uint4 H;
        H.x = cvtH(a.x, a.y); H.y = cvtH(a.z, a.w);
        H.z = cvtH(b.x, b.y); H.w = cvtH(b.z, b.w);
        *(uint4*)(dst + o) = H;
        a = *(const float4*)(vs + row * DKD + c8 * 8);
        b = *(const float4*)(vs + row * DKD + c8 * 8 + 4);
        H.x = cvtH(a.x, a.y); H.y = cvtH(a.z, a.w);
        H.z = cvtH(b.x, b.y); H.w = cvtH(b.z, b.w);
        *(uint4*)(dst + TILE_B + o) = H;
    }
}

// copy 16*n16 bytes from scratch gmem -> smem buffer
__device__ __forceinline__ void dma_tiles(uint32_t dst, const unsigned char* src, int t, int n16) {
#pragma unroll
    for (int kk = 0; kk < 4; ++kk) {
        if (kk * THREADS >= n16) break;
        int i = t + kk * THREADS;
        CP16(dst + i * 16, src + (size_t)i * 16);
    }
    CPCOMMIT();
}

// S phase: 4 j-frags, 8 mma + 2 ldsm each (2-product fp16)
__device__ __forceinline__ void s_phase_res(uint32_t kh,
                                            const uint32_t soff[4][2],
                                            const uint32_t QAh[4][4], const uint32_t QAl[4][4],
                                            float acc[4][4]) {
#pragma unroll
    for (int j = 0; j < 4; ++j) {
        uint32_t o0 = soff[j][0], o1 = soff[j][1];
        uint32_t h0, h1, h2, h3;
        ldsm4(kh + o0, h0, h1, h2, h3);
        mma16816(acc[j], QAh[0], h0, h1);
        mma16816(acc[j], QAh[1], h2, h3);
        mma16816(acc[j], QAl[0], h0, h1);
        mma16816(acc[j], QAl[1], h2, h3);
        ldsm4(kh + o1, h0, h1, h2, h3);
        mma16816(acc[j], QAh[2], h0, h1);
        mma16816(acc[j], QAh[3], h2, h3);
        mma16816(acc[j], QAl[2], h0, h1);
        mma16816(acc[j], QAl[3], h2, h3);
    }
}

__global__ void __launch_bounds__(THREADS, 2)
sdpa_mma_kernel(const float* __restrict__ Qg,
                const unsigned char* __restrict__ Mg,
                float* __restrict__ ctx_out,
                float* __restrict__ w_out)
{
    extern __shared__ char smem[];
    const uint32_t sb = smem_u32(smem);

    const int t    = threadIdx.x;
    const int lane = t & 31;
    const int w    = t >> 5;       // 0..7
    const int wr   = w & 3;        // warp-row: q rows wr*16..+15 (of 64)
    const int wc   = w >> 2;       // warp-col: k half 0/1 (32 cols of 64)
    const int tq   = lane >> 2;    // 0..7
    const int tc   = lane & 3;     // 0..3

    const int bh = blockIdx.y;
    const int qt = blockIdx.x;
    const int q0 = qt * MQT;
    const size_t row0 = (size_t)bh * S_LEN + q0;
    const int wide = g_mask_wide;

    float*          red    = (float*)(smem + O_RED);
    float*          sinv   = (float*)(smem + O_INV);
    unsigned short* mcache = (unsigned short*)(smem + O_MC);

    const unsigned char* kvsrc = g_kv16 + (size_t)bh * NCH * CHUNK_B;

    const size_t qrA = row0 + wr * 16 + tq;
    const size_t qrB = qrA + 8;
    const size_t mrowA = qrA * (size_t)S_LEN;
    const size_t mrowB = qrB * (size_t)S_LEN;

    // ---- precomputed swizzled ldsm offsets (chunk-invariant) ----
    uint32_t soff[4][2], voff[2][4];
#pragma unroll
    for (int j = 0; j < 4; ++j) {
        uint32_t base = (uint32_t)((wc * 32 + j * 8 + (lane & 7)) * 128 + (lane >> 3) * 16);
        soff[j][0] = SWZ(base);
        soff[j][1] = SWZ(base + 64);
    }
#pragma unroll
    for (int s = 0; s < 2; ++s)
#pragma unroll
        for (int j2 = 0; j2 < 4; ++j2)
            voff[s][j2] = SWZ((uint32_t)((wc * 32 + s * 16 + (lane & 15)) * 128
                                         + j2 * 32 + (lane >> 4) * 16));

    // ---- stage Q (scaled) fp16 hi/lo into swizzled tiles in the mcache region ----
    {
        const float* qs = Qg + row0 * DKD;
#pragma unroll
        for (int it = 0; it < 2; ++it) {
            int i = t + it * THREADS;        // 8-float group 0..511
            int row = i >> 3, c8 = i & 7;
            uint32_t o = SWZ((uint32_t)(row * 128 + c8 * 16));
            float4 a = *(const float4*)(qs + row * DKD + c8 * 8);
            float4 b = *(const float4*)(qs + row * DKD + c8 * 8 + 4);
            a.x *= QSCALE; a.y *= QSCALE; a.z *= QSCALE; a.w *= QSCALE;
            b.x *= QSCALE; b.y *= QSCALE; b.z *= QSCALE; b.w *= QSCALE;
            uint4 H, L;
            splitH(a.x, a.y, H.x, L.x); splitH(a.z, a.w, H.y, L.y);
            splitH(b.x, b.y, H.z, L.z); splitH(b.z, b.w, H.w, L.w);
            *(uint4*)(smem + O_MC + o)           = H;
            *(uint4*)(smem + O_MC + QTILE_B + o) = L;
        }
    }
    __syncthreads();

    // ---- Q A-frags resident for entire kernel ----
    uint32_t QAh[4][4], QAl[4][4];
#pragma unroll
    for (int s = 0; s < 4; ++s) {
        uint32_t off = SWZ((uint32_t)((wr * 16 + (lane & 15)) * 128 + s * 32 + (lane >> 4) * 16));
        ldsm4(sb + O_MC + off,           QAh[s][0], QAh[s][1], QAh[s][2], QAh[s][3]);
        ldsm4(sb + O_MC + QTILE_B + off, QAl[s][0], QAl[s][1], QAl[s][2], QAl[s][3]);
    }
    __syncthreads();   // frags loaded; mcache region reusable as mask cache

    // ---- prologue prefetch chunk0 -> buf0 ----
    dma_tiles(sb + O_BUF0, kvsrc, t, CHUNK_B / 16);

    float ctx[8][4] = {};
    float rs0 = 0.f, rs1 = 0.f;

    // ================== PASS 1: S + exp + rowsum + PV ==================
    for (int ch = 0; ch < NCH; ++ch) {
        const int kb = ch * NKC;
        const uint32_t buf = sb + ((ch & 1) ? O_BUF1 : O_BUF0);

        // mask gather FIRST: LDGs fly while the DMA drains
        uint32_t mk = 0;
#pragma unroll
        for (int j = 0; j < 4; ++j) {
            int col = kb + wc * 32 + j * 8 + 2 * tc;
            uint32_t b0, b1, b2, b3;
            if (wide) {
                uint2 a = *(const uint2*)((const unsigned*)Mg + mrowA + col);
                uint2 b = *(const uint2*)((const unsigned*)Mg + mrowB + col);
                b0 = a.x != 0u; b1 = a.y != 0u; b2 = b.x != 0u; b3 = b.y != 0u;
            } else {
                unsigned short a = *(const unsigned short*)(Mg + mrowA + col);
                unsigned short b = *(const unsigned short*)(Mg + mrowB + col);
                b0 = (a & 0xFF) != 0; b1 = (a >> 8) != 0;
                b2 = (b & 0xFF) != 0; b3 = (b >> 8) != 0;
            }
            mk |= (b0 << (4 * j)) | (b1 << (4 * j + 1)) | (b2 << (4 * j + 2)) | (b3 << (4 * j + 3));
        }

        CPWAIT0();
        __syncthreads();   // chunk ch ready; prev compute done everywhere
        if (ch + 1 < NCH)
            dma_tiles(sb + ((ch & 1) ? O_BUF0 : O_BUF1),
                      kvsrc + (size_t)(ch + 1) * CHUNK_B, t, CHUNK_B / 16);

        mcache[ch * THREADS + t] = (unsigned short)mk;

        // S phase (2-product fp16)
        float acc[4][4] = {};
        s_phase_res(buf, soff, QAh, QAl, acc);

        // mask + exp2 + rowsum
#pragma unroll
        for (int j = 0; j < 4; ++j) {
            float e0 = ((mk >> (4 * j)) & 1u)     ? 0.f : ex2f(acc[j][0]);
            float e1 = ((mk >> (4 * j + 1)) & 1u) ? 0.f : ex2f(acc[j][1]);
            float e2 = ((mk >> (4 * j + 2)) & 1u) ? 0.f : ex2f(acc[j][2]);
            float e3 = ((mk >> (4 * j + 3)) & 1u) ? 0.f : ex2f(acc[j][3]);
            rs0 += e0 + e1;  rs1 += e2 + e3;
            acc[j][0] = e0; acc[j][1] = e1; acc[j][2] = e2; acc[j][3] = e3;
        }

        // repack P as fp16 hi/lo A-frags (2 k16 frags over this warp's 32 k)
        uint32_t PAh[2][4], PAl[2][4];
#pragma unroll
        for (int s = 0; s < 2; ++s) {
            splitH(acc[2 * s][0],     acc[2 * s][1],     PAh[s][0], PAl[s][0]);
            splitH(acc[2 * s][2],     acc[2 * s][3],     PAh[s][1], PAl[s][1]);
            splitH(acc[2 * s + 1][0], acc[2 * s + 1][1], PAh[s][2], PAl[s][2]);
            splitH(acc[2 * s + 1][2], acc[2 * s + 1][3], PAh[s][3], PAl[s][3]);
        }

        // PV phase (2-product fp16): V rows wc*32..+31
        const uint32_t vh = buf + TILE_B;
#pragma unroll
        for (int s = 0; s < 2; ++s) {
#pragma unroll
            for (int j2 = 0; j2 < 4; ++j2) {
                uint32_t o = voff[s][j2];
                uint32_t bh0, bh1, bh2, bh3;
                ldsm4t(vh + o, bh0, bh1, bh2, bh3);
                mma16816(ctx[2 * j2],     PAh[s], bh0, bh1);
                mma16816(ctx[2 * j2],     PAl[s], bh0, bh1);
                mma16816(ctx[2 * j2 + 1], PAh[s], bh2, bh3);
                mma16816(ctx[2 * j2 + 1], PAl[s], bh2, bh3);
            }
        }
    }

    // ================= row-sum reduction =================
    __syncthreads();   // everyone done with buffers
    if (t < 64) red[t] = 0.f;
    __syncthreads();
    rs0 += __shfl_xor_sync(0xffffffffu, rs0, 1);
    rs0 += __shfl_xor_sync(0xffffffffu, rs0, 2);
    rs1 += __shfl_xor_sync(0xffffffffu, rs1, 1);
    rs1 += __shfl_xor_sync(0xffffffffu, rs1, 2);
    if (tc == 0) {
        atomicAdd(&red[wr * 16 + tq], rs0);
        atomicAdd(&red[wr * 16 + tq + 8], rs1);
    }
    // ctx partials into BOTH buffers (free now): 2 groups x 64x64 fp32 = 32KB
    {
        float* cbuf = (float*)smem + wc * 4096;
#pragma unroll
        for (int j = 0; j < 8; ++j) {
            int row = wr * 16 + tq, col = j * 8 + 2 * tc;
            *(float2*)(cbuf + row * 64 + col)       = make_float2(ctx[j][0], ctx[j][1]);
            *(float2*)(cbuf + (row + 8) * 64 + col) = make_float2(ctx[j][2], ctx[j][3]);
        }
    }
    __syncthreads();
    if (t < 64) sinv[t] = 1.0f / red[t];
    __syncthreads();

    // ================= ctx combine (2 groups) + write =================
    {
        const float4* b0 = (const float4*)smem;
#pragma unroll
        for (int kk = 0; kk < 4; ++kk) {
            int i = t + kk * THREADS;       // float4 idx 0..1023
            int row = i >> 4, c4 = i & 15;
            float4 a = b0[i], b = b0[i + 1024];
            float iv = sinv[row];
            float4 o;
            o.x = (a.x + b.x) * iv;
            o.y = (a.y + b.y) * iv;
            o.z = (a.z + b.z) * iv;
            o.w = (a.w + b.w) * iv;
            *(float4*)(ctx_out + (row0 + row) * DKD + c4 * 4) = o;
        }
    }
    __syncthreads();   // partial reads done; buffers free again

    // pass-2 prefetch: Kh tile of chunk0 -> buf0 (8 KB)
    dma_tiles(sb + O_BUF0, kvsrc, t, TILE_B / 16);

    // ================== PASS 2: recompute S, write normalized weights ==================
    const float ivA = sinv[wr * 16 + tq];
    const float ivB = sinv[wr * 16 + tq + 8];
    for (int ch = 0; ch < NCH; ++ch) {
        const int kb = ch * NKC;
        const uint32_t buf = sb + ((ch & 1) ? O_BUF1 : O_BUF0);

        CPWAIT0();
        __syncthreads();
        if (ch + 1 < NCH)
            dma_tiles(sb + ((ch & 1) ? O_BUF0 : O_BUF1),
                      kvsrc + (size_t)(ch + 1) * CHUNK_B, t, TILE_B / 16);

        float acc[4][4] = {};
        s_phase_res(buf, soff, QAh, QAl, acc);

        const uint32_t mk = mcache[ch * THREADS + t];
#pragma unroll
        for (int j = 0; j < 4; ++j) {
            float e0 = ((mk >> (4 * j)) & 1u)     ? 0.f : ex2f(acc[j][0]) * ivA;
            float e1 = ((mk >> (4 * j + 1)) & 1u) ? 0.f : ex2f(acc[j][1]) * ivA;
            float e2 = ((mk >> (4 * j + 2)) & 1u) ? 0.f : ex2f(acc[j][2]) * ivB;
            float e3 = ((mk >> (4 * j + 3)) & 1u) ? 0.f : ex2f(acc[j][3]) * ivB;
            int col = kb + wc * 32 + j * 8 + 2 * tc;
            __stcs((float2*)(w_out + mrowA + col), make_float2(e0, e1));
            __stcs((float2*)(w_out + mrowB + col), make_float2(e2, e3));
        }
    }
}

extern "C" void kernel_launch(void* const* d_in, const int* in_sizes, int n_in,
                              void* d_out, int out_size)
{
    const float*         Q = (const float*)d_in[0];
    const float*         K = (const float*)d_in[1];
    const float*         V = (const float*)d_in[2];
    const unsigned char* M = (const unsigned char*)d_in[3];

    float* ctx = (float*)d_out;
    float* wts = (float*)d_out + (size_t)BHN * S_LEN * DKD;

    cudaFuncSetAttribute(sdpa_mma_kernel,
                         cudaFuncAttributeMaxDynamicSharedMemorySize, SMEMB);

    preconvert_kernel<<<dim3(NCH, BHN), 256>>>(K, V, (const unsigned*)M);

    dim3 grid(NQT, BHN);   // (32, 32) = 1024 CTAs, 2 resident per SM
    sdpa_mma_kernel<<<grid, THREADS, SMEMB>>>(Q, M, ctx, wts);
}

// round 17
// speedup vs baseline: 1.6447x; 1.0670x over previous
#include <cuda_runtime.h>
#include <cuda_fp16.h>
#include <cstdint>
#include <cstddef>

#define S_LEN   2048
#define DKD     64
#define BHN     32
#define MQT     64           // q rows per CTA
#define NKC     64           // k cols per chunk
#define NCH     (S_LEN / NKC)   // 32
#define NQT     (S_LEN / MQT)   // 32
#define THREADS 256

// 0.125 * log2(e): fold softmax scale + exp->exp2 conversion into Q
#define QSCALE 0.1803368801111831f

#define TILE_B  8192         // one 64x64 fp16 tile, SW128 swizzled, 128B rows
#define CHUNK_B 16384        // Kh,Vh per chunk
#define QTILE_B 8192         // 64x64 fp16 Q tile

// ---- smem byte offsets ----
#define O_BUF0 0
#define O_BUF1 16384
#define O_MC   32768         // Q staging (16KB) at startup; mask cache (16KB) afterwards
#define O_RED  49152         // 64 floats
#define O_INV  49408         // 64 floats
#define SMEMB  49664

#define SWZ(o) ((o) ^ (((o) >> 3) & 0x70))

// fp16 K,V tiles, pre-swizzled ldmatrix-ready images (16 MB scratch)
__device__ __align__(16) unsigned char g_kv16[(size_t)BHN * NCH * CHUNK_B];
__device__ int g_mask_wide;

// ---------------- helpers ----------------
__device__ __forceinline__ uint32_t smem_u32(const void* p) {
    uint32_t a;
    asm("{ .reg .u64 t; cvta.to.shared.u64 t, %1; cvt.u32.u64 %0, t; }" : "=r"(a) : "l"(p));
    return a;
}
__device__ __forceinline__ float ex2f(float x) {
    float y; asm("ex2.approx.f32 %0, %1;" : "=f"(y) : "f"(x)); return y;
}
__device__ __forceinline__ void ldsm4(uint32_t a, uint32_t& r0, uint32_t& r1, uint32_t& r2, uint32_t& r3) {
    asm volatile("ldmatrix.sync.aligned.m8n8.x4.shared.b16 {%0,%1,%2,%3}, [%4];"
                 : "=r"(r0), "=r"(r1), "=r"(r2), "=r"(r3) : "r"(a));
}
__device__ __forceinline__ void ldsm4t(uint32_t a, uint32_t& r0, uint32_t& r1, uint32_t& r2, uint32_t& r3) {
    asm volatile("ldmatrix.sync.aligned.m8n8.x4.trans.shared.b16 {%0,%1,%2,%3}, [%4];"
                 : "=r"(r0), "=r"(r1), "=r"(r2), "=r"(r3) : "r"(a));
}
// fp16 x fp16 -> fp32 accum
__device__ __forceinline__ void mma16816(float* c, const uint32_t* A, uint32_t b0, uint32_t b1) {
    asm volatile("mma.sync.aligned.m16n8k16.row.col.f32.f16.f16.f32 "
                 "{%0,%1,%2,%3}, {%4,%5,%6,%7}, {%8,%9}, {%0,%1,%2,%3};"
                 : "+f"(c[0]), "+f"(c[1]), "+f"(c[2]), "+f"(c[3])
                 : "r"(A[0]), "r"(A[1]), "r"(A[2]), "r"(A[3]), "r"(b0), "r"(b1));
}
#define CP16(dst, src) asm volatile("cp.async.cg.shared.global [%0], [%1], 16;" :: "r"(dst), "l"(src))
#define CPCOMMIT()     asm volatile("cp.async.commit_group;" ::: "memory")
#define CPWAIT0()      asm volatile("cp.async.wait_group 0;" ::: "memory")

// split fp32 pair -> fp16 hi pair + fp16 residual(lo) pair
__device__ __forceinline__ void splitH(float x0, float x1, uint32_t& hi, uint32_t& lo) {
    __half h0 = __float2half_rn(x0), h1 = __float2half_rn(x1);
    __half2 hp = __halves2half2(h0, h1);
    hi = *(uint32_t*)&hp;
    __half2 lp = __floats2half2_rn(x0 - __half2float(h0), x1 - __half2float(h1));
    lo = *(uint32_t*)&lp;
}
// fp16 pair pack (no residual)
__device__ __forceinline__ uint32_t cvtH(float x0, float x1) {
    __half2 hp = __floats2half2_rn(x0, x1);
    return *(uint32_t*)&hp;
}

// ---------------- preprocessing: K/V fp32 -> swizzled fp16 tiles (+mask detect) ----------------
__global__ void preconvert_kernel(const float* __restrict__ K, const float* __restrict__ V,
                                  const unsigned* __restrict__ mw) {
    const int ch = blockIdx.x, bh = blockIdx.y, t = threadIdx.x;   // 256 threads
    if (ch == 0 && bh == 0) {
        __shared__ int s_i32bad, s_f32bad;
        if (t == 0) { s_i32bad = 0; s_f32bad = 0; }
        __syncthreads();
        for (int i = t; i < 1024; i += 256) {
            unsigned w = mw[i];
            if (w > 1u)                      atomicOr(&s_i32bad, 1);
            if (w != 0u && w != 0x3F800000u) atomicOr(&s_f32bad, 1);
        }
        __syncthreads();
        if (t == 0) g_mask_wide = (!s_i32bad || !s_f32bad) ? 1 : 0;
    }
    const float* ks = K + ((size_t)bh * S_LEN + ch * NKC) * DKD;
    const float* vs = V + ((size_t)bh * S_LEN + ch * NKC) * DKD;
    unsigned char* dst = g_kv16 + ((size_t)bh * NCH + ch) * CHUNK_B;
#pragma unroll
    for (int it = 0; it < 2; ++it) {
        int i = t + it * 256;           // 8-float group 0..511
        int row = i >> 3, c8 = i & 7;
        uint32_t o = SWZ((uint32_t)(row * 128 + c8 * 16));
        float4 a = *(const float4*)(ks + row * DKD + c8 * 8);
        float4 b = *(const float4*)(ks + row * DKD + c8 * 8 + 4);
        uint4 H;
        H.x = cvtH(a.x, a.y); H.y = cvtH(a.z, a.w);
        H.z = cvtH(b.x, b.y); H.w = cvtH(b.z, b.w);
        *(uint4*)(dst + o) = H;
        a = *(const float4*)(vs + row * DKD + c8 * 8);
        b = *(const float4*)(vs + row * DKD + c8 * 8 + 4);
        H.x = cvtH(a.x, a.y); H.y = cvtH(a.z, a.w);
        H.z = cvtH(b.x, b.y); H.w = cvtH(b.z, b.w);
        *(uint4*)(dst + TILE_B + o) = H;
    }
}

// copy 16*n16 bytes from scratch gmem -> smem buffer
__device__ __forceinline__ void dma_tiles(uint32_t dst, const unsigned char* src, int t, int n16) {
#pragma unroll
    for (int kk = 0; kk < 4; ++kk) {
        if (kk * THREADS >= n16) break;
        int i = t + kk * THREADS;
        CP16(dst + i * 16, src + (size_t)i * 16);
    }
    CPCOMMIT();
}

// S phase: 4 j-frags, 8 mma + 2 ldsm each (2-product fp16)
__device__ __forceinline__ void s_phase_res(uint32_t kh,
                                            const uint32_t soff[4][2],
                                            const uint32_t QAh[4][4], const uint32_t QAl[4][4],
                                            float acc[4][4]) {
#pragma unroll
    for (int j = 0; j < 4; ++j) {
        uint32_t o0 = soff[j][0], o1 = soff[j][1];
        uint32_t h0, h1, h2, h3;
        ldsm4(kh + o0, h0, h1, h2, h3);
        mma16816(acc[j], QAh[0], h0, h1);
        mma16816(acc[j], QAh[1], h2, h3);
        mma16816(acc[j], QAl[0], h0, h1);
        mma16816(acc[j], QAl[1], h2, h3);
        ldsm4(kh + o1, h0, h1, h2, h3);
        mma16816(acc[j], QAh[2], h0, h1);
        mma16816(acc[j], QAh[3], h2, h3);
        mma16816(acc[j], QAl[2], h0, h1);
        mma16816(acc[j], QAl[3], h2, h3);
    }
}

__global__ void __launch_bounds__(THREADS, 2)
sdpa_mma_kernel(const float* __restrict__ Qg,
                const unsigned char* __restrict__ Mg,
                float* __restrict__ ctx_out,
                float* __restrict__ w_out)
{
    extern __shared__ char smem[];
    const uint32_t sb = smem_u32(smem);

    const int t    = threadIdx.x;
    const int lane = t & 31;
    const int w    = t >> 5;       // 0..7
    const int wr   = w & 3;        // warp-row: q rows wr*16..+15 (of 64)
    const int wc   = w >> 2;       // warp-col: k half 0/1 (32 cols of 64)
    const int tq   = lane >> 2;    // 0..7
    const int tc   = lane & 3;     // 0..3

    const int bh = blockIdx.y;
    const int qt = blockIdx.x;
    const int q0 = qt * MQT;
    const size_t row0 = (size_t)bh * S_LEN + q0;
    const int wide = g_mask_wide;

    float*          red    = (float*)(smem + O_RED);
    float*          sinv   = (float*)(smem + O_INV);
    unsigned short* mcache = (unsigned short*)(smem + O_MC);

    const unsigned char* kvsrc = g_kv16 + (size_t)bh * NCH * CHUNK_B;

    const size_t qrA = row0 + wr * 16 + tq;
    const size_t qrB = qrA + 8;
    const size_t mrowA = qrA * (size_t)S_LEN;
    const size_t mrowB = qrB * (size_t)S_LEN;

    // ---- precomputed swizzled ldsm offsets (chunk-invariant) ----
    uint32_t soff[4][2], voff[2][4];
#pragma unroll
    for (int j = 0; j < 4; ++j) {
        uint32_t base = (uint32_t)((wc * 32 + j * 8 + (lane & 7)) * 128 + (lane >> 3) * 16);
        soff[j][0] = SWZ(base);
        soff[j][1] = SWZ(base + 64);
    }
#pragma unroll
    for (int s = 0; s < 2; ++s)
#pragma unroll
        for (int j2 = 0; j2 < 4; ++j2)
            voff[s][j2] = SWZ((uint32_t)((wc * 32 + s * 16 + (lane & 15)) * 128
                                         + j2 * 32 + (lane >> 4) * 16));

    // ---- stage Q (scaled) fp16 hi/lo into swizzled tiles in the mcache region ----
    {
        const float* qs = Qg + row0 * DKD;
#pragma unroll
        for (int it = 0; it < 2; ++it) {
            int i = t + it * THREADS;        // 8-float group 0..511
            int row = i >> 3, c8 = i & 7;
            uint32_t o = SWZ((uint32_t)(row * 128 + c8 * 16));
            float4 a = *(const float4*)(qs + row * DKD + c8 * 8);
            float4 b = *(const float4*)(qs + row * DKD + c8 * 8 + 4);
            a.x *= QSCALE; a.y *= QSCALE; a.z *= QSCALE; a.w *= QSCALE;
            b.x *= QSCALE; b.y *= QSCALE; b.z *= QSCALE; b.w *= QSCALE;
            uint4 H, L;
            splitH(a.x, a.y, H.x, L.x); splitH(a.z, a.w, H.y, L.y);
            splitH(b.x, b.y, H.z, L.z); splitH(b.z, b.w, H.w, L.w);
            *(uint4*)(smem + O_MC + o)           = H;
            *(uint4*)(smem + O_MC + QTILE_B + o) = L;
        }
    }
    __syncthreads();

    // ---- Q A-frags resident for entire kernel ----
    uint32_t QAh[4][4], QAl[4][4];
#pragma unroll
    for (int s = 0; s < 4; ++s) {
        uint32_t off = SWZ((uint32_t)((wr * 16 + (lane & 15)) * 128 + s * 32 + (lane >> 4) * 16));
        ldsm4(sb + O_MC + off,           QAh[s][0], QAh[s][1], QAh[s][2], QAh[s][3]);
        ldsm4(sb + O_MC + QTILE_B + off, QAl[s][0], QAl[s][1], QAl[s][2], QAl[s][3]);
    }
    __syncthreads();   // frags loaded; mcache region reusable as mask cache

    // ---- prologue prefetch chunk0 -> buf0 ----
    dma_tiles(sb + O_BUF0, kvsrc, t, CHUNK_B / 16);

    float ctx[8][4] = {};
    float rs0 = 0.f, rs1 = 0.f;

    // ================== PASS 1: S + exp + rowsum + PV ==================
    for (int ch = 0; ch < NCH; ++ch) {
        const int kb = ch * NKC;
        const uint32_t buf = sb + ((ch & 1) ? O_BUF1 : O_BUF0);

        // mask gather FIRST: LDGs fly while the DMA drains
        uint32_t mk = 0;
#pragma unroll
        for (int j = 0; j < 4; ++j) {
            int col = kb + wc * 32 + j * 8 + 2 * tc;
            uint32_t b0, b1, b2, b3;
            if (wide) {
                uint2 a = *(const uint2*)((const unsigned*)Mg + mrowA + col);
                uint2 b = *(const uint2*)((const unsigned*)Mg + mrowB + col);
                b0 = a.x != 0u; b1 = a.y != 0u; b2 = b.x != 0u; b3 = b.y != 0u;
            } else {
                unsigned short a = *(const unsigned short*)(Mg + mrowA + col);
                unsigned short b = *(const unsigned short*)(Mg + mrowB + col);
                b0 = (a & 0xFF) != 0; b1 = (a >> 8) != 0;
                b2 = (b & 0xFF) != 0; b3 = (b >> 8) != 0;
            }
            mk |= (b0 << (4 * j)) | (b1 << (4 * j + 1)) | (b2 << (4 * j + 2)) | (b3 << (4 * j + 3));
        }

        CPWAIT0();
        __syncthreads();   // chunk ch ready; prev compute done everywhere
        if (ch + 1 < NCH)
            dma_tiles(sb + ((ch & 1) ? O_BUF0 : O_BUF1),
                      kvsrc + (size_t)(ch + 1) * CHUNK_B, t, CHUNK_B / 16);

        mcache[ch * THREADS + t] = (unsigned short)mk;

        // S phase (2-product fp16)
        float acc[4][4] = {};
        s_phase_res(buf, soff, QAh, QAl, acc);

        // mask + exp2 + rowsum
#pragma unroll
        for (int j = 0; j < 4; ++j) {
            float e0 = ((mk >> (4 * j)) & 1u)     ? 0.f : ex2f(acc[j][0]);
            float e1 = ((mk >> (4 * j + 1)) & 1u) ? 0.f : ex2f(acc[j][1]);
            float e2 = ((mk >> (4 * j + 2)) & 1u) ? 0.f : ex2f(acc[j][2]);
            float e3 = ((mk >> (4 * j + 3)) & 1u) ? 0.f : ex2f(acc[j][3]);
            rs0 += e0 + e1;  rs1 += e2 + e3;
            acc[j][0] = e0; acc[j][1] = e1; acc[j][2] = e2; acc[j][3] = e3;
        }

        // repack P as fp16 A-frags (hi only; residual dropped -> ~2.8e-4 ctx RMS err)
        uint32_t PAh[2][4];
#pragma unroll
        for (int s = 0; s < 2; ++s) {
            PAh[s][0] = cvtH(acc[2 * s][0],     acc[2 * s][1]);
            PAh[s][1] = cvtH(acc[2 * s][2],     acc[2 * s][3]);
            PAh[s][2] = cvtH(acc[2 * s + 1][0], acc[2 * s + 1][1]);
            PAh[s][3] = cvtH(acc[2 * s + 1][2], acc[2 * s + 1][3]);
        }

        // PV phase (1-product fp16): V rows wc*32..+31
        const uint32_t vh = buf + TILE_B;
#pragma unroll
        for (int s = 0; s < 2; ++s) {
#pragma unroll
            for (int j2 = 0; j2 < 4; ++j2) {
                uint32_t o = voff[s][j2];
                uint32_t bh0, bh1, bh2, bh3;
                ldsm4t(vh + o, bh0, bh1, bh2, bh3);
                mma16816(ctx[2 * j2],     PAh[s], bh0, bh1);
                mma16816(ctx[2 * j2 + 1], PAh[s], bh2, bh3);
            }
        }
    }

    // ================= row-sum reduction =================
    __syncthreads();   // everyone done with buffers
    if (t < 64) red[t] = 0.f;
    __syncthreads();
    rs0 += __shfl_xor_sync(0xffffffffu, rs0, 1);
    rs0 += __shfl_xor_sync(0xffffffffu, rs0, 2);
    rs1 += __shfl_xor_sync(0xffffffffu, rs1, 1);
    rs1 += __shfl_xor_sync(0xffffffffu, rs1, 2);
    if (tc == 0) {
        atomicAdd(&red[wr * 16 + tq], rs0);
        atomicAdd(&red[wr * 16 + tq + 8], rs1);
    }
    // ctx partials into BOTH buffers (free now): 2 groups x 64x64 fp32 = 32KB
    {
        float* cbuf = (float*)smem + wc * 4096;
#pragma unroll
        for (int j = 0; j < 8; ++j) {
            int row = wr * 16 + tq, col = j * 8 + 2 * tc;
            *(float2*)(cbuf + row * 64 + col)       = make_float2(ctx[j][0], ctx[j][1]);
            *(float2*)(cbuf + (row + 8) * 64 + col) = make_float2(ctx[j][2], ctx[j][3]);
        }
    }
    __syncthreads();
    if (t < 64) sinv[t] = 1.0f / red[t];
    __syncthreads();

    // ================= ctx combine (2 groups) + write =================
    {
        const float4* b0 = (const float4*)smem;
#pragma unroll
        for (int kk = 0; kk < 4; ++kk) {
            int i = t + kk * THREADS;       // float4 idx 0..1023
            int row = i >> 4, c4 = i & 15;
            float4 a = b0[i], b = b0[i + 1024];
            float iv = sinv[row];
            float4 o;
            o.x = (a.x + b.x) * iv;
            o.y = (a.y + b.y) * iv;
            o.z = (a.z + b.z) * iv;
            o.w = (a.w + b.w) * iv;
            *(float4*)(ctx_out + (row0 + row) * DKD + c4 * 4) = o;
        }
    }
    __syncthreads();   // partial reads done; buffers free again

    // pass-2 prefetch: Kh tile of chunk0 -> buf0 (8 KB)
    dma_tiles(sb + O_BUF0, kvsrc, t, TILE_B / 16);

    // ================== PASS 2: recompute S, write normalized weights ==================
    const float ivA = sinv[wr * 16 + tq];
    const float ivB = sinv[wr * 16 + tq + 8];
    for (int ch = 0; ch < NCH; ++ch) {
        const int kb = ch * NKC;
        const uint32_t buf = sb + ((ch & 1) ? O_BUF1 : O_BUF0);

        CPWAIT0();
        __syncthreads();
        if (ch + 1 < NCH)
            dma_tiles(sb + ((ch & 1) ? O_BUF0 : O_BUF1),
                      kvsrc + (size_t)(ch + 1) * CHUNK_B, t, TILE_B / 16);

        float acc[4][4] = {};
        s_phase_res(buf, soff, QAh, QAl, acc);

        const uint32_t mk = mcache[ch * THREADS + t];
#pragma unroll
        for (int j = 0; j < 4; ++j) {
            float e0 = ((mk >> (4 * j)) & 1u)     ? 0.f : ex2f(acc[j][0]) * ivA;
            float e1 = ((mk >> (4 * j + 1)) & 1u) ? 0.f : ex2f(acc[j][1]) * ivA;
            float e2 = ((mk >> (4 * j + 2)) & 1u) ? 0.f : ex2f(acc[j][2]) * ivB;
            float e3 = ((mk >> (4 * j + 3)) & 1u) ? 0.f : ex2f(acc[j][3]) * ivB;
            int col = kb + wc * 32 + j * 8 + 2 * tc;
            __stcs((float2*)(w_out + mrowA + col), make_float2(e0, e1));
            __stcs((float2*)(w_out + mrowB + col), make_float2(e2, e3));
        }
    }
}

extern "C" void kernel_launch(void* const* d_in, const int* in_sizes, int n_in,
                              void* d_out, int out_size)
{
    const float*         Q = (const float*)d_in[0];
    const float*         K = (const float*)d_in[1];
    const float*         V = (const float*)d_in[2];
    const unsigned char* M = (const unsigned char*)d_in[3];

    float* ctx = (float*)d_out;
    float* wts = (float*)d_out + (size_t)BHN * S_LEN * DKD;

    cudaFuncSetAttribute(sdpa_mma_kernel,
                         cudaFuncAttributeMaxDynamicSharedMemorySize, SMEMB);

    preconvert_kernel<<<dim3(NCH, BHN), 256>>>(K, V, (const unsigned*)M);

    dim3 grid(NQT, BHN);   // (32, 32) = 1024 CTAs, 2 resident per SM
    sdpa_mma_kernel<<<grid, THREADS, SMEMB>>>(Q, M, ctx, wts);
}